// round 16
// baseline (speedup 1.0000x reference)
#include <cuda_runtime.h>
#include <cstdint>

#define N_NODES 50000
#define C_DIM   128
#define E_EDGES 800000
#define NBUCK   65536
#define CANDMAX 256
#define BCAP    64         // bucket capacity per node (E[deg]=16, P(>=64)~1e-18)
#define OVMAX   4096       // overflow safety net

typedef unsigned long long ull;
#define MASK52 ((1ull << 52) - 1ull)
#define INV32  (1.0f / 4294967296.0f)

// ---------------- scratch (static device globals; no allocation) ----------------
__device__ ull      g_degp[N_NODES];                     // packed: cnt<<52 | wsum(32.32)
__device__ __align__(8) int2 g_bkt[N_NODES * BCAP];      // 25.6 MB: (src, ew-bits)
__device__ int      g_ovfn;
__device__ __align__(16) int4 g_ovf[OVMAX];              // (src, ew-bits, dst, 0)
__device__ __align__(16) unsigned g_keys[N_NODES + 12];  // padded for uint4 sweep
__device__ __align__(16) int g_hist[NBUCK];
__device__ __align__(16) float g_Xt[C_DIM * C_DIM];
__device__ __align__(16) float g_gi[C_DIM * 3 * C_DIM];
__device__ __align__(16) float g_gh[C_DIM * 3 * C_DIM];
__device__ __align__(16) float g_Wnew[C_DIM * C_DIM];

// ---------------- side stream + events (created pre-main; no device memory) ----------------
struct HxSide {
    cudaStream_t s1;
    cudaEvent_t  evf, evj;
    HxSide() {
        cudaStreamCreateWithFlags(&s1, cudaStreamNonBlocking);
        cudaEventCreateWithFlags(&evf, cudaEventDisableTiming);
        cudaEventCreateWithFlags(&evj, cudaEventDisableTiming);
    }
};
static HxSide hx;

// ---------------- init A: packed degrees + overflow counter (main chain) ----------------
__global__ void k_initA() {
    int i = blockIdx.x * blockDim.x + threadIdx.x;
    if (i < N_NODES) g_degp[i] = (1ull << 32);   // self-loop weight 1.0, count 0
    if (i == 0)      g_ovfn = 0;
}

// ---------------- init B: histogram + key pad (side chain) ----------------
__global__ void k_initB() {
    int i = blockIdx.x * blockDim.x + threadIdx.x;
    if (i < NBUCK) g_hist[i] = 0;
    if (i < 12)    g_keys[N_NODES + i] = 0u;     // pad never passes threshold
}

// ---------------- single edge pass: packed degree atomic gives bucket slot ----------------
__global__ void k_bucket(const int* __restrict__ ei, const float* __restrict__ ew) {
    int e = blockIdx.x * 256 + threadIdx.x;
    if (e >= E_EDGES) return;
    int src = ei[e];
    int dst = ei[E_EDGES + e];
    float w = ew[e];
    ull v = (ull)(w * 4294967296.0f) + (1ull << 52);
    ull old = atomicAdd(&g_degp[dst], v);
    int pos = (int)(old >> 52);
    if (pos < BCAP) {
        g_bkt[dst * BCAP + pos] = make_int2(src, __float_as_int(w));
    } else {
        int o = atomicAdd(&g_ovfn, 1);
        if (o < OVMAX) g_ovf[o] = make_int4(src, __float_as_int(w), dst, 0);
    }
}

// ---------------- scores + key histogram (warp per node, pnorm fused) ----------------
__global__ void k_score(const float* __restrict__ X, const float* __restrict__ p) {
    __shared__ float4 ps[32];
    __shared__ float spinv;
    if (threadIdx.x < 32) {
        float4 q = ((const float4*)p)[threadIdx.x];
        ps[threadIdx.x] = q;
        float ss = q.x * q.x + q.y * q.y + q.z * q.z + q.w * q.w;
        #pragma unroll
        for (int o = 16; o; o >>= 1) ss += __shfl_xor_sync(0xffffffffu, ss, o);
        if (threadIdx.x == 0) spinv = rsqrtf(ss);
    }
    __syncthreads();
    int w    = (blockIdx.x * blockDim.x + threadIdx.x) >> 5;
    int lane = threadIdx.x & 31;
    if (w >= N_NODES) return;
    float4 x  = ((const float4*)X)[w * 32 + lane];
    float4 pp = ps[lane];
    float d = x.x * pp.x + x.y * pp.y + x.z * pp.z + x.w * pp.w;
    for (int o = 16; o; o >>= 1) d += __shfl_xor_sync(0xffffffffu, d, o);
    if (lane == 0) {
        float s = d * spinv;
        unsigned bits = __float_as_uint(s);
        unsigned key  = (bits & 0x80000000u) ? ~bits : (bits ^ 0x80000000u);
        g_keys[w] = key;
        atomicAdd(&g_hist[key >> 16], 1);
    }
}

// ---------------- fused select: parallel thresh + compact + top-128 + X_tilde ----------------
__global__ void __launch_bounds__(1024)
k_select(const float* __restrict__ X) {
    __shared__ ull  s[CANDMAX];
    __shared__ int  wscan[32];
    __shared__ int  hh[64 + 1];
    __shared__ int  scnt;
    __shared__ int  schunk;
    __shared__ int  sthresh;
    __shared__ int   sidx[C_DIM];
    __shared__ float sgate[C_DIM];
    int t    = threadIdx.x;
    int lane = t & 31;
    int wid  = t >> 5;

    // --- phase 1a: per-thread bucket sums + parallel block scan -> chunk ---
    if (t == 0) scnt = 0;
    int v;
    {
        const int4* h4 = (const int4*)(g_hist + t * 64);
        int sum = 0;
        #pragma unroll
        for (int b = 0; b < 16; b++) {
            int4 q = h4[b];
            sum += q.x + q.y + q.z + q.w;
        }
        v = sum;
    }
    int sc = v;
    #pragma unroll
    for (int d = 1; d < 32; d <<= 1) {
        int tmp = __shfl_up_sync(0xffffffffu, sc, d);
        if (lane >= d) sc += tmp;
    }
    if (lane == 31) wscan[wid] = sc;
    __syncthreads();
    if (wid == 0) {
        int ws = wscan[lane];
        #pragma unroll
        for (int d = 1; d < 32; d <<= 1) {
            int tmp = __shfl_up_sync(0xffffffffu, ws, d);
            if (lane >= d) ws += tmp;
        }
        wscan[lane] = ws;
    }
    __syncthreads();
    int incl  = sc + ((wid > 0) ? wscan[wid - 1] : 0);
    int total = wscan[31];
    int sfx_excl = total - incl;                          // keys in buckets > mine
    if (sfx_excl < C_DIM && sfx_excl + v >= C_DIM) schunk = t;   // unique
    __syncthreads();
    int chunk = schunk;
    if (t == chunk) hh[64] = sfx_excl;
    __syncthreads();
    int cumAbove = hh[64];

    // --- phase 1b: parallel 64-entry suffix scan within chunk -> exact threshold ---
    if (t < 64) hh[t] = g_hist[chunk * 64 + t];
    __syncthreads();
    #pragma unroll
    for (int d = 1; d < 64; d <<= 1) {
        int add = 0;
        if (t < 64 && t + d < 64) add = hh[t + d];
        __syncthreads();
        if (t < 64) hh[t] += add;                         // suffix-inclusive
        __syncthreads();
    }
    if (t < 64) {
        int si  = cumAbove + hh[t];
        int sxe = (t == 63) ? cumAbove : cumAbove + hh[t + 1];
        if (sxe < C_DIM && si >= C_DIM) sthresh = chunk * 64 + t;
    }
    __syncthreads();
    int th = sthresh;

    // --- phase 2: vectorized compact (2x-unrolled uint4 sweep) ---
    {
        const uint4* k4 = (const uint4*)g_keys;
        const int NV = (N_NODES + 12) / 4;
        for (int i = t; i < NV; i += 2048) {
            uint4 q0 = k4[i];
            uint4 q1 = (i + 1024 < NV) ? k4[i + 1024] : make_uint4(0, 0, 0, 0);
            #pragma unroll
            for (int j = 0; j < 4; j++) {
                unsigned key = (j == 0) ? q0.x : (j == 1) ? q0.y : (j == 2) ? q0.z : q0.w;
                if ((int)(key >> 16) >= th) {
                    int pos = atomicAdd(&scnt, 1);
                    if (pos < CANDMAX)
                        s[pos] = ((ull)key << 32) |
                                 (unsigned)(0xFFFFFFFFu - (unsigned)(i * 4 + j));
                }
            }
            #pragma unroll
            for (int j = 0; j < 4; j++) {
                unsigned key = (j == 0) ? q1.x : (j == 1) ? q1.y : (j == 2) ? q1.z : q1.w;
                if ((int)(key >> 16) >= th) {
                    int pos = atomicAdd(&scnt, 1);
                    if (pos < CANDMAX)
                        s[pos] = ((ull)key << 32) |
                                 (unsigned)(0xFFFFFFFFu - (unsigned)((i + 1024) * 4 + j));
                }
            }
        }
    }
    __syncthreads();
    int cnt = scnt; if (cnt > CANDMAX) cnt = CANDMAX;
    if (t < CANDMAX && t >= cnt) s[t] = 0ull;
    __syncthreads();

    // --- phase 3: bitonic sort (256, ascending) on 256 threads w/ named barrier ---
    if (t < CANDMAX) {
        for (int k2 = 2; k2 <= CANDMAX; k2 <<= 1)
            for (int j = k2 >> 1; j > 0; j >>= 1) {
                int i = t;
                int ixj = i ^ j;
                if (ixj > i) {
                    ull a = s[i], b = s[ixj];
                    bool asc = ((i & k2) == 0);
                    if (asc ? (a > b) : (a < b)) { s[i] = b; s[ixj] = a; }
                }
                asm volatile("bar.sync 1, 256;" ::: "memory");
            }
    }
    __syncthreads();

    // --- phase 4: extract top-128 (descending), gate, gather X_tilde ---
    if (t < C_DIM) {
        ull comp = s[CANDMAX - 1 - t];
        unsigned key = (unsigned)(comp >> 32);
        int idx = (int)(0xFFFFFFFFu - (unsigned)comp);
        unsigned bits = (key & 0x80000000u) ? (key ^ 0x80000000u) : ~key;
        sidx[t]  = idx;
        sgate[t] = tanhf(__uint_as_float(bits));
    }
    __syncthreads();
    for (int i = t; i < C_DIM * C_DIM; i += 1024) {
        int r = i >> 7, c = i & 127;
        g_Xt[i] = X[sidx[r] * C_DIM + c] * sgate[r];
    }
}

// ---------------- GRU GEMM, small tiles: BM=32 BN=64, grid (4,6) ----------------
// mode 0: gi = Xt@W_ih^T ; mode 1: gh = Wc@W_hh^T
__global__ void __launch_bounds__(256)
k_gru(int mode, const float* __restrict__ Wc, const float* __restrict__ Wih,
      const float* __restrict__ Whh) {
    const float* A = (mode == 0) ? g_Xt : Wc;
    const float* B = (mode == 0) ? Wih  : Whh;
    float* Cm      = (mode == 0) ? g_gi : g_gh;
    const int Nn = 3 * C_DIM;

    extern __shared__ float sg[];
    float* Bs = sg;                 // [64][129]
    float* As = sg + 64 * 129;      // [32][128]
    int tid = threadIdx.x;
    int bx = blockIdx.x, by = blockIdx.y;

    #pragma unroll
    for (int it = 0; it < 32; it++) {               // B tile 64x128
        int flat = tid + it * 256;
        int n = flat >> 7, k = flat & 127;
        Bs[n * 129 + k] = B[(by * 64 + n) * C_DIM + k];
    }
    #pragma unroll
    for (int it = 0; it < 16; it++) {               // A tile 32x128
        int flat = tid + it * 256;
        As[flat] = A[bx * 32 * C_DIM + flat];
    }
    __syncthreads();

    int tx = tid & 31, ty = tid >> 5;
    float acc[4][2];
    #pragma unroll
    for (int i = 0; i < 4; i++) { acc[i][0] = 0.0f; acc[i][1] = 0.0f; }

    const float* Ap  = As + ty * 4 * 128;
    const float* Bp0 = Bs + tx * 129;
    const float* Bp1 = Bs + (tx + 32) * 129;
    #pragma unroll 4
    for (int k4 = 0; k4 < 32; k4++) {
        float4 a4[4];
        #pragma unroll
        for (int i = 0; i < 4; i++)
            a4[i] = *(const float4*)(Ap + i * 128 + k4 * 4);
        float c00 = Bp0[k4*4], c01 = Bp0[k4*4+1], c02 = Bp0[k4*4+2], c03 = Bp0[k4*4+3];
        float c10 = Bp1[k4*4], c11 = Bp1[k4*4+1], c12 = Bp1[k4*4+2], c13 = Bp1[k4*4+3];
        #pragma unroll
        for (int i = 0; i < 4; i++) {
            acc[i][0] += a4[i].x * c00 + a4[i].y * c01 + a4[i].z * c02 + a4[i].w * c03;
            acc[i][1] += a4[i].x * c10 + a4[i].y * c11 + a4[i].z * c12 + a4[i].w * c13;
        }
    }
    #pragma unroll
    for (int i = 0; i < 4; i++) {
        int gr = bx * 32 + ty * 4 + i;
        Cm[gr * Nn + by * 64 + tx]      = acc[i][0];
        Cm[gr * Nn + by * 64 + tx + 32] = acc[i][1];
    }
}

// ---------------- GRU gates -> W_new ----------------
__global__ void k_gates(const float* __restrict__ b_ih, const float* __restrict__ b_hh,
                        const float* __restrict__ Wc) {
    int i = blockIdx.x * 256 + threadIdx.x;
    if (i >= C_DIM * C_DIM) return;
    int b = i >> 7, j = i & 127;
    float gir = g_gi[b * 384 + j]       + b_ih[j];
    float ghr = g_gh[b * 384 + j]       + b_hh[j];
    float giz = g_gi[b * 384 + 128 + j] + b_ih[128 + j];
    float ghz = g_gh[b * 384 + 128 + j] + b_hh[128 + j];
    float gin = g_gi[b * 384 + 256 + j] + b_ih[256 + j];
    float ghn = g_gh[b * 384 + 256 + j] + b_hh[256 + j];
    float r = 1.0f / (1.0f + expf(-(gir + ghr)));
    float z = 1.0f / (1.0f + expf(-(giz + ghz)));
    float n = tanhf(gin + r * ghn);
    g_Wnew[i] = (1.0f - z) * n + z * Wc[i];
}

// ---------------- FUSED aggregate + GEMM: out = D^-1(A+I)D^-1 X @ Wnew^T + bias ----------------
// Per block: gather/aggregate 64 node rows directly into k-major smem, then f32x2 GEMM.
__global__ void __launch_bounds__(256, 2)
k_fused(const float* __restrict__ X, float* __restrict__ out,
        const float* __restrict__ bias) {
    extern __shared__ float sm2[];
    float* Ast = sm2;                  // [128 k][68 m]
    float* Bst = sm2 + 128 * 68;       // [128 k][130 n]
    int tid  = threadIdx.x;
    int lane = tid & 31;
    int wid  = tid >> 5;
    int row0 = blockIdx.x * 64;

    // B: Wnew[n][k] -> Bst[k][n]
    #pragma unroll 8
    for (int it = 0; it < 64; it++) {
        int flat = tid + it * 256;
        int k = flat & 127, n = flat >> 7;
        Bst[k * 130 + n] = g_Wnew[n * C_DIM + k];
    }

    // aggregate 8 nodes per warp into registers (lane owns k = 4*lane..4*lane+3)
    float acc[8][4];
    #pragma unroll
    for (int i = 0; i < 8; i++) {
        int gn = row0 + wid * 8 + i;
        if (gn < N_NODES) {
            ull d = g_degp[gn];
            int cnt = (int)(d >> 52);
            float di = rsqrtf(__ull2float_rn(d & MASK52) * INV32);
            float4 x = ((const float4*)X)[gn * 32 + lane];
            float ax = x.x * di, ay = x.y * di, az = x.z * di, aw = x.w * di;
            const int2* row = g_bkt + gn * BCAP;
            int inb = (cnt < BCAP) ? cnt : BCAP;
            if (inb > 0) {
                int2 c = row[0];
                for (int e = 0; e < inb; e++) {
                    int2 cn = (e + 1 < inb) ? row[e + 1] : c;
                    ull ds = g_degp[c.x];
                    float s = rsqrtf(__ull2float_rn(ds & MASK52) * INV32) *
                              __int_as_float(c.y);
                    float4 xs = ((const float4*)X)[c.x * 32 + lane];
                    ax += xs.x * s; ay += xs.y * s; az += xs.z * s; aw += xs.w * s;
                    c = cn;
                }
            }
            if (cnt > BCAP) {                     // astronomically rare; exact fixup
                int n = g_ovfn; if (n > OVMAX) n = OVMAX;
                for (int o = 0; o < n; o++) {
                    int4 c = g_ovf[o];
                    if (c.z == gn) {
                        ull ds = g_degp[c.x];
                        float s = rsqrtf(__ull2float_rn(ds & MASK52) * INV32) *
                                  __int_as_float(c.y);
                        float4 xs = ((const float4*)X)[c.x * 32 + lane];
                        ax += xs.x * s; ay += xs.y * s; az += xs.z * s; aw += xs.w * s;
                    }
                }
            }
            acc[i][0] = ax * di; acc[i][1] = ay * di;
            acc[i][2] = az * di; acc[i][3] = aw * di;
        } else {
            acc[i][0] = acc[i][1] = acc[i][2] = acc[i][3] = 0.0f;
        }
    }
    // transpose-store to k-major Ast (8-node amortized float4 stores)
    #pragma unroll
    for (int j = 0; j < 4; j++) {
        int k = 4 * lane + j;
        float4 v0 = make_float4(acc[0][j], acc[1][j], acc[2][j], acc[3][j]);
        float4 v1 = make_float4(acc[4][j], acc[5][j], acc[6][j], acc[7][j]);
        *(float4*)(Ast + k * 68 + wid * 8)     = v0;
        *(float4*)(Ast + k * 68 + wid * 8 + 4) = v1;
    }
    __syncthreads();

    // f32x2 GEMM (identical to previous k_gemm2 mainloop)
    int tx = tid & 31, ty = tid >> 5;
    int m0 = ty * 8;
    ull accd[4][4];
    #pragma unroll
    for (int i = 0; i < 4; i++)
        #pragma unroll
        for (int j = 0; j < 4; j++) accd[i][j] = 0ull;

    #pragma unroll 2
    for (int k = 0; k < 128; k++) {
        double2 ad0 = *(const double2*)(Ast + k * 68 + m0);
        double2 ad1 = *(const double2*)(Ast + k * 68 + m0 + 4);
        ull a[4];
        a[0] = __double_as_longlong(ad0.x);
        a[1] = __double_as_longlong(ad0.y);
        a[2] = __double_as_longlong(ad1.x);
        a[3] = __double_as_longlong(ad1.y);
        ull bb[4];
        #pragma unroll
        for (int j = 0; j < 4; j++) {
            float b = Bst[k * 130 + tx + 32 * j];
            asm("mov.b64 %0, {%1, %1};" : "=l"(bb[j]) : "f"(b));
        }
        #pragma unroll
        for (int i = 0; i < 4; i++)
            #pragma unroll
            for (int j = 0; j < 4; j++)
                asm("fma.rn.f32x2 %0, %1, %2, %0;" : "+l"(accd[i][j]) : "l"(a[i]), "l"(bb[j]));
    }

    float bv[4];
    #pragma unroll
    for (int j = 0; j < 4; j++) bv[j] = bias[tx + 32 * j];
    #pragma unroll
    for (int i = 0; i < 4; i++) {
        int gr0 = row0 + m0 + 2 * i;
        int gr1 = gr0 + 1;
        #pragma unroll
        for (int j = 0; j < 4; j++) {
            float clo, chi;
            asm("mov.b64 {%0, %1}, %2;" : "=f"(clo), "=f"(chi) : "l"(accd[i][j]));
            if (gr0 < N_NODES) out[gr0 * C_DIM + tx + 32 * j] = clo + bv[j];
            if (gr1 < N_NODES) out[gr1 * C_DIM + tx + 32 * j] = chi + bv[j];
        }
    }
}

// ---------------- launch ----------------
extern "C" void kernel_launch(void* const* d_in, const int* in_sizes, int n_in,
                              void* d_out, int out_size) {
    const float* X      = (const float*)d_in[0];
    const float* ew     = (const float*)d_in[1];
    const float* p      = (const float*)d_in[2];
    const float* W_ih   = (const float*)d_in[3];
    const float* W_hh   = (const float*)d_in[4];
    const float* b_ih   = (const float*)d_in[5];
    const float* b_hh   = (const float*)d_in[6];
    const float* W_conv = (const float*)d_in[7];
    const float* b_conv = (const float*)d_in[8];
    const int*   ei     = (const int*)d_in[9];     // int32 (JAX x64 disabled)
    float* out = (float*)d_out;

    const int GRU_SMEM   = (64 * 129 + 32 * 128) * sizeof(float);    // 49408 B
    const int FUSED_SMEM = (128 * 68 + 128 * 130) * sizeof(float);   // 101376 B
    cudaFuncSetAttribute(k_gru,   cudaFuncAttributeMaxDynamicSharedMemorySize, GRU_SMEM);
    cudaFuncSetAttribute(k_fused, cudaFuncAttributeMaxDynamicSharedMemorySize, FUSED_SMEM);

    // ---- fork at t=0: chain B (topk/GRU) on side stream ----
    cudaEventRecord(hx.evf, 0);
    cudaStreamWaitEvent(hx.s1, hx.evf, 0);

    k_initB <<<256, 256, 0, hx.s1>>>();
    k_gru   <<<dim3(4, 6), 256, GRU_SMEM, hx.s1>>>(1, W_conv, W_ih, W_hh);  // gh: no deps
    k_score <<<(N_NODES + 7) / 8, 256, 0, hx.s1>>>(X, p);
    k_select<<<1, 1024, 0, hx.s1>>>(X);
    k_gru   <<<dim3(4, 6), 256, GRU_SMEM, hx.s1>>>(0, W_conv, W_ih, W_hh);  // gi: needs Xt
    k_gates <<<64, 256, 0, hx.s1>>>(b_ih, b_hh, W_conv);
    cudaEventRecord(hx.evj, hx.s1);

    // ---- chain A on main stream: initA -> bucket ----
    k_initA <<<(N_NODES + 255) / 256, 256>>>();
    k_bucket<<<(E_EDGES + 255) / 256, 256>>>(ei, ew);

    // ---- join, then fused aggregate+GEMM ----
    cudaStreamWaitEvent(0, hx.evj, 0);
    k_fused<<<(N_NODES + 63) / 64, 256, FUSED_SMEM>>>(X, out, b_conv);
}

// round 17
// speedup vs baseline: 1.2116x; 1.2116x over previous
#include <cuda_runtime.h>
#include <cstdint>

#define N_NODES 50000
#define C_DIM   128
#define E_EDGES 800000
#define NBUCK   65536
#define CANDMAX 256
#define BCAP    64         // bucket capacity per node (E[deg]=16, P(>=64)~1e-18)
#define OVMAX   4096       // overflow safety net

typedef unsigned long long ull;
#define MASK52 ((1ull << 52) - 1ull)
#define INV32  (1.0f / 4294967296.0f)

// ---------------- scratch (static device globals; no allocation) ----------------
__device__ ull      g_degp[N_NODES];                     // packed: cnt<<52 | wsum(32.32)
__device__ float    g_dinv[N_NODES];
__device__ __align__(16) float g_agg[N_NODES * C_DIM];   // 25.6 MB
__device__ __align__(8) int2 g_bkt[N_NODES * BCAP];      // 25.6 MB: (src, ew-bits)
__device__ int      g_ovfn;
__device__ __align__(16) int4 g_ovf[OVMAX];              // (src, ew-bits, dst, 0)
__device__ __align__(16) unsigned g_keys[N_NODES + 12];  // padded for uint4 sweep
__device__ __align__(16) int g_hist[NBUCK];
__device__ __align__(16) float g_Xt[C_DIM * C_DIM];
__device__ __align__(16) float g_gi[C_DIM * 3 * C_DIM];
__device__ __align__(16) float g_gh[C_DIM * 3 * C_DIM];
__device__ __align__(16) float g_Wnew[C_DIM * C_DIM];

// ---------------- side stream + events (created pre-main; no device memory) ----------------
struct HxSide {
    cudaStream_t s1;
    cudaEvent_t  evf, evj;
    HxSide() {
        cudaStreamCreateWithFlags(&s1, cudaStreamNonBlocking);
        cudaEventCreateWithFlags(&evf, cudaEventDisableTiming);
        cudaEventCreateWithFlags(&evj, cudaEventDisableTiming);
    }
};
static HxSide hx;

// ---------------- init A: packed degrees + overflow counter (main chain) ----------------
__global__ void k_initA() {
    int i = blockIdx.x * blockDim.x + threadIdx.x;
    if (i < N_NODES) g_degp[i] = (1ull << 32);   // self-loop weight 1.0, count 0
    if (i == 0)      g_ovfn = 0;
}

// ---------------- init B: histogram + key pad (side chain) ----------------
__global__ void k_initB() {
    int i = blockIdx.x * blockDim.x + threadIdx.x;
    if (i < NBUCK) g_hist[i] = 0;
    if (i < 12)    g_keys[N_NODES + i] = 0u;     // pad never passes threshold
}

// ---------------- single edge pass: packed degree atomic gives bucket slot ----------------
__global__ void k_bucket(const int* __restrict__ ei, const float* __restrict__ ew) {
    int e = blockIdx.x * 256 + threadIdx.x;
    if (e >= E_EDGES) return;
    int src = ei[e];
    int dst = ei[E_EDGES + e];
    float w = ew[e];
    ull v = (ull)(w * 4294967296.0f) + (1ull << 52);
    ull old = atomicAdd(&g_degp[dst], v);
    int pos = (int)(old >> 52);
    if (pos < BCAP) {
        g_bkt[dst * BCAP + pos] = make_int2(src, __float_as_int(w));
    } else {
        int o = atomicAdd(&g_ovfn, 1);
        if (o < OVMAX) g_ovf[o] = make_int4(src, __float_as_int(w), dst, 0);
    }
}

// ---------------- dinv from packed weight sum ----------------
__global__ void k_dinv() {
    int i = blockIdx.x * 256 + threadIdx.x;
    if (i < N_NODES) {
        ull d = g_degp[i];
        float w = __ull2float_rn(d & MASK52) * INV32;
        g_dinv[i] = rsqrtf(w);                    // w >= 1 always
    }
}

// ---------------- atomic-free aggregation: warp per node, bucket walk + inline overflow ----------------
__global__ void k_agg(const float* __restrict__ X) {
    int gt   = blockIdx.x * blockDim.x + threadIdx.x;
    int w    = gt >> 5;
    int lane = gt & 31;
    if (w >= N_NODES) return;
    int cnt = (int)(g_degp[w] >> 52);
    float di = g_dinv[w];
    float4 x = ((const float4*)X)[w * 32 + lane];
    float4 acc = make_float4(x.x * di, x.y * di, x.z * di, x.w * di);  // self-loop: di*x
    const int2* row = g_bkt + w * BCAP;
    int inb = (cnt < BCAP) ? cnt : BCAP;
    if (inb > 0) {
        int2 c = row[0];
        for (int e = 0; e < inb; e++) {
            int2 cn = (e + 1 < inb) ? row[e + 1] : c;   // prefetch next entry
            float s = g_dinv[c.x] * __int_as_float(c.y);
            float4 xs = ((const float4*)X)[c.x * 32 + lane];
            acc.x += xs.x * s; acc.y += xs.y * s;
            acc.z += xs.z * s; acc.w += xs.w * s;
            c = cn;
        }
    }
    if (cnt > BCAP) {                             // astronomically rare; exact fixup
        int n = g_ovfn; if (n > OVMAX) n = OVMAX;
        for (int i = 0; i < n; i++) {
            int4 c = g_ovf[i];
            if (c.z == w) {
                float s = g_dinv[c.x] * __int_as_float(c.y);
                float4 xs = ((const float4*)X)[c.x * 32 + lane];
                acc.x += xs.x * s; acc.y += xs.y * s;
                acc.z += xs.z * s; acc.w += xs.w * s;
            }
        }
    }
    acc.x *= di; acc.y *= di; acc.z *= di; acc.w *= di;  // outer dinv[dst]
    ((float4*)g_agg)[w * 32 + lane] = acc;
}

// ---------------- scores + key histogram (warp per node, pnorm fused) ----------------
__global__ void k_score(const float* __restrict__ X, const float* __restrict__ p) {
    __shared__ float4 ps[32];
    __shared__ float spinv;
    if (threadIdx.x < 32) {
        float4 q = ((const float4*)p)[threadIdx.x];
        ps[threadIdx.x] = q;
        float ss = q.x * q.x + q.y * q.y + q.z * q.z + q.w * q.w;
        #pragma unroll
        for (int o = 16; o; o >>= 1) ss += __shfl_xor_sync(0xffffffffu, ss, o);
        if (threadIdx.x == 0) spinv = rsqrtf(ss);
    }
    __syncthreads();
    int w    = (blockIdx.x * blockDim.x + threadIdx.x) >> 5;
    int lane = threadIdx.x & 31;
    if (w >= N_NODES) return;
    float4 x  = ((const float4*)X)[w * 32 + lane];
    float4 pp = ps[lane];
    float d = x.x * pp.x + x.y * pp.y + x.z * pp.z + x.w * pp.w;
    for (int o = 16; o; o >>= 1) d += __shfl_xor_sync(0xffffffffu, d, o);
    if (lane == 0) {
        float s = d * spinv;
        unsigned bits = __float_as_uint(s);
        unsigned key  = (bits & 0x80000000u) ? ~bits : (bits ^ 0x80000000u);
        g_keys[w] = key;
        atomicAdd(&g_hist[key >> 16], 1);
    }
}

// ---------------- fused select: parallel thresh + compact + top-128 + X_tilde ----------------
__global__ void __launch_bounds__(1024)
k_select(const float* __restrict__ X) {
    __shared__ ull  s[CANDMAX];
    __shared__ int  wscan[32];
    __shared__ int  hh[64 + 1];
    __shared__ int  scnt;
    __shared__ int  schunk;
    __shared__ int  sthresh;
    __shared__ int   sidx[C_DIM];
    __shared__ float sgate[C_DIM];
    int t    = threadIdx.x;
    int lane = t & 31;
    int wid  = t >> 5;

    // --- phase 1a: per-thread bucket sums + parallel block scan -> chunk ---
    if (t == 0) scnt = 0;
    int v;
    {
        const int4* h4 = (const int4*)(g_hist + t * 64);
        int sum = 0;
        #pragma unroll
        for (int b = 0; b < 16; b++) {
            int4 q = h4[b];
            sum += q.x + q.y + q.z + q.w;
        }
        v = sum;
    }
    int sc = v;
    #pragma unroll
    for (int d = 1; d < 32; d <<= 1) {
        int tmp = __shfl_up_sync(0xffffffffu, sc, d);
        if (lane >= d) sc += tmp;
    }
    if (lane == 31) wscan[wid] = sc;
    __syncthreads();
    if (wid == 0) {
        int ws = wscan[lane];
        #pragma unroll
        for (int d = 1; d < 32; d <<= 1) {
            int tmp = __shfl_up_sync(0xffffffffu, ws, d);
            if (lane >= d) ws += tmp;
        }
        wscan[lane] = ws;
    }
    __syncthreads();
    int incl  = sc + ((wid > 0) ? wscan[wid - 1] : 0);
    int total = wscan[31];
    int sfx_excl = total - incl;                          // keys in buckets > mine
    if (sfx_excl < C_DIM && sfx_excl + v >= C_DIM) schunk = t;   // unique
    __syncthreads();
    int chunk = schunk;
    if (t == chunk) hh[64] = sfx_excl;
    __syncthreads();
    int cumAbove = hh[64];

    // --- phase 1b: parallel 64-entry suffix scan within chunk -> exact threshold ---
    if (t < 64) hh[t] = g_hist[chunk * 64 + t];
    __syncthreads();
    #pragma unroll
    for (int d = 1; d < 64; d <<= 1) {
        int add = 0;
        if (t < 64 && t + d < 64) add = hh[t + d];
        __syncthreads();
        if (t < 64) hh[t] += add;                         // suffix-inclusive
        __syncthreads();
    }
    if (t < 64) {
        int si  = cumAbove + hh[t];
        int sxe = (t == 63) ? cumAbove : cumAbove + hh[t + 1];
        if (sxe < C_DIM && si >= C_DIM) sthresh = chunk * 64 + t;
    }
    __syncthreads();
    int th = sthresh;

    // --- phase 2: vectorized compact (2x-unrolled uint4 sweep) ---
    {
        const uint4* k4 = (const uint4*)g_keys;
        const int NV = (N_NODES + 12) / 4;
        for (int i = t; i < NV; i += 2048) {
            uint4 q0 = k4[i];
            uint4 q1 = (i + 1024 < NV) ? k4[i + 1024] : make_uint4(0, 0, 0, 0);
            #pragma unroll
            for (int j = 0; j < 4; j++) {
                unsigned key = (j == 0) ? q0.x : (j == 1) ? q0.y : (j == 2) ? q0.z : q0.w;
                if ((int)(key >> 16) >= th) {
                    int pos = atomicAdd(&scnt, 1);
                    if (pos < CANDMAX)
                        s[pos] = ((ull)key << 32) |
                                 (unsigned)(0xFFFFFFFFu - (unsigned)(i * 4 + j));
                }
            }
            #pragma unroll
            for (int j = 0; j < 4; j++) {
                unsigned key = (j == 0) ? q1.x : (j == 1) ? q1.y : (j == 2) ? q1.z : q1.w;
                if ((int)(key >> 16) >= th) {
                    int pos = atomicAdd(&scnt, 1);
                    if (pos < CANDMAX)
                        s[pos] = ((ull)key << 32) |
                                 (unsigned)(0xFFFFFFFFu - (unsigned)((i + 1024) * 4 + j));
                }
            }
        }
    }
    __syncthreads();
    int cnt = scnt; if (cnt > CANDMAX) cnt = CANDMAX;
    if (t < CANDMAX && t >= cnt) s[t] = 0ull;
    __syncthreads();

    // --- phase 3: bitonic sort (256, ascending) on 256 threads w/ named barrier ---
    if (t < CANDMAX) {
        for (int k2 = 2; k2 <= CANDMAX; k2 <<= 1)
            for (int j = k2 >> 1; j > 0; j >>= 1) {
                int i = t;
                int ixj = i ^ j;
                if (ixj > i) {
                    ull a = s[i], b = s[ixj];
                    bool asc = ((i & k2) == 0);
                    if (asc ? (a > b) : (a < b)) { s[i] = b; s[ixj] = a; }
                }
                asm volatile("bar.sync 1, 256;" ::: "memory");
            }
    }
    __syncthreads();

    // --- phase 4: extract top-128 (descending), gate, gather X_tilde ---
    if (t < C_DIM) {
        ull comp = s[CANDMAX - 1 - t];
        unsigned key = (unsigned)(comp >> 32);
        int idx = (int)(0xFFFFFFFFu - (unsigned)comp);
        unsigned bits = (key & 0x80000000u) ? (key ^ 0x80000000u) : ~key;
        sidx[t]  = idx;
        sgate[t] = tanhf(__uint_as_float(bits));
    }
    __syncthreads();
    for (int i = t; i < C_DIM * C_DIM; i += 1024) {
        int r = i >> 7, c = i & 127;
        g_Xt[i] = X[sidx[r] * C_DIM + c] * sgate[r];
    }
}

// ---------------- GRU GEMM, small tiles: BM=32 BN=64, grid (4,6) ----------------
// mode 0: gi = Xt@W_ih^T ; mode 1: gh = Wc@W_hh^T
__global__ void __launch_bounds__(256)
k_gru(int mode, const float* __restrict__ Wc, const float* __restrict__ Wih,
      const float* __restrict__ Whh) {
    const float* A = (mode == 0) ? g_Xt : Wc;
    const float* B = (mode == 0) ? Wih  : Whh;
    float* Cm      = (mode == 0) ? g_gi : g_gh;
    const int Nn = 3 * C_DIM;

    extern __shared__ float sg[];
    float* Bs = sg;                 // [64][129]
    float* As = sg + 64 * 129;      // [32][128]
    int tid = threadIdx.x;
    int bx = blockIdx.x, by = blockIdx.y;

    #pragma unroll
    for (int it = 0; it < 32; it++) {               // B tile 64x128
        int flat = tid + it * 256;
        int n = flat >> 7, k = flat & 127;
        Bs[n * 129 + k] = B[(by * 64 + n) * C_DIM + k];
    }
    #pragma unroll
    for (int it = 0; it < 16; it++) {               // A tile 32x128
        int flat = tid + it * 256;
        As[flat] = A[bx * 32 * C_DIM + flat];
    }
    __syncthreads();

    int tx = tid & 31, ty = tid >> 5;
    float acc[4][2];
    #pragma unroll
    for (int i = 0; i < 4; i++) { acc[i][0] = 0.0f; acc[i][1] = 0.0f; }

    const float* Ap  = As + ty * 4 * 128;
    const float* Bp0 = Bs + tx * 129;
    const float* Bp1 = Bs + (tx + 32) * 129;
    #pragma unroll 4
    for (int k4 = 0; k4 < 32; k4++) {
        float4 a4[4];
        #pragma unroll
        for (int i = 0; i < 4; i++)
            a4[i] = *(const float4*)(Ap + i * 128 + k4 * 4);
        float c00 = Bp0[k4*4], c01 = Bp0[k4*4+1], c02 = Bp0[k4*4+2], c03 = Bp0[k4*4+3];
        float c10 = Bp1[k4*4], c11 = Bp1[k4*4+1], c12 = Bp1[k4*4+2], c13 = Bp1[k4*4+3];
        #pragma unroll
        for (int i = 0; i < 4; i++) {
            acc[i][0] += a4[i].x * c00 + a4[i].y * c01 + a4[i].z * c02 + a4[i].w * c03;
            acc[i][1] += a4[i].x * c10 + a4[i].y * c11 + a4[i].z * c12 + a4[i].w * c13;
        }
    }
    #pragma unroll
    for (int i = 0; i < 4; i++) {
        int gr = bx * 32 + ty * 4 + i;
        Cm[gr * Nn + by * 64 + tx]      = acc[i][0];
        Cm[gr * Nn + by * 64 + tx + 32] = acc[i][1];
    }
}

// ---------------- GRU gates -> W_new ----------------
__global__ void k_gates(const float* __restrict__ b_ih, const float* __restrict__ b_hh,
                        const float* __restrict__ Wc) {
    int i = blockIdx.x * 256 + threadIdx.x;
    if (i >= C_DIM * C_DIM) return;
    int b = i >> 7, j = i & 127;
    float gir = g_gi[b * 384 + j]       + b_ih[j];
    float ghr = g_gh[b * 384 + j]       + b_hh[j];
    float giz = g_gi[b * 384 + 128 + j] + b_ih[128 + j];
    float ghz = g_gh[b * 384 + 128 + j] + b_hh[128 + j];
    float gin = g_gi[b * 384 + 256 + j] + b_ih[256 + j];
    float ghn = g_gh[b * 384 + 256 + j] + b_hh[256 + j];
    float r = 1.0f / (1.0f + expf(-(gir + ghr)));
    float z = 1.0f / (1.0f + expf(-(giz + ghz)));
    float n = tanhf(gin + r * ghn);
    g_Wnew[i] = (1.0f - z) * n + z * Wc[i];
}

// ---------------- final GEMM, BN=128 full-width, packed fma.rn.f32x2 ----------------
// out[m,n] = sum_k agg[m,k]*Wnew[n,k] + bias[n]
__global__ void __launch_bounds__(256, 2)
k_gemm2(float* __restrict__ out, const float* __restrict__ bias) {
    extern __shared__ float sm2[];
    float* Ast = sm2;                  // [128 k][68 m]
    float* Bst = sm2 + 128 * 68;       // [128 k][130 n]
    int tid = threadIdx.x;
    int row0 = blockIdx.x * 64;

    #pragma unroll 8
    for (int it = 0; it < 64; it++) {               // B: Wnew[n][k] -> Bst[k][n]
        int flat = tid + it * 256;
        int k = flat & 127, n = flat >> 7;
        Bst[k * 130 + n] = g_Wnew[n * C_DIM + k];
    }
    #pragma unroll 4
    for (int it = 0; it < 32; it++) {               // A: agg[row0+r][k] -> Ast[k][r]
        int flat = tid + it * 256;
        int k = flat & 127, r = flat >> 7;
        int gr = row0 + r;
        Ast[k * 68 + r] = (gr < N_NODES) ? g_agg[gr * C_DIM + k] : 0.0f;
    }
    __syncthreads();

    int tx = tid & 31, ty = tid >> 5;
    int m0 = ty * 8;
    ull acc[4][4];
    #pragma unroll
    for (int i = 0; i < 4; i++)
        #pragma unroll
        for (int j = 0; j < 4; j++) acc[i][j] = 0ull;

    #pragma unroll 2
    for (int k = 0; k < 128; k++) {
        double2 ad0 = *(const double2*)(Ast + k * 68 + m0);      // rows m0..m0+3
        double2 ad1 = *(const double2*)(Ast + k * 68 + m0 + 4);  // rows m0+4..m0+7
        ull a[4];
        a[0] = __double_as_longlong(ad0.x);
        a[1] = __double_as_longlong(ad0.y);
        a[2] = __double_as_longlong(ad1.x);
        a[3] = __double_as_longlong(ad1.y);
        ull bb[4];
        #pragma unroll
        for (int j = 0; j < 4; j++) {
            float b = Bst[k * 130 + tx + 32 * j];
            asm("mov.b64 %0, {%1, %1};" : "=l"(bb[j]) : "f"(b));
        }
        #pragma unroll
        for (int i = 0; i < 4; i++)
            #pragma unroll
            for (int j = 0; j < 4; j++)
                asm("fma.rn.f32x2 %0, %1, %2, %0;" : "+l"(acc[i][j]) : "l"(a[i]), "l"(bb[j]));
    }

    float bv[4];
    #pragma unroll
    for (int j = 0; j < 4; j++) bv[j] = bias[tx + 32 * j];
    #pragma unroll
    for (int i = 0; i < 4; i++) {
        int gr0 = row0 + m0 + 2 * i;
        int gr1 = gr0 + 1;
        #pragma unroll
        for (int j = 0; j < 4; j++) {
            float clo, chi;
            asm("mov.b64 {%0, %1}, %2;" : "=f"(clo), "=f"(chi) : "l"(acc[i][j]));
            if (gr0 < N_NODES) out[gr0 * C_DIM + tx + 32 * j] = clo + bv[j];
            if (gr1 < N_NODES) out[gr1 * C_DIM + tx + 32 * j] = chi + bv[j];
        }
    }
}

// ---------------- launch ----------------
extern "C" void kernel_launch(void* const* d_in, const int* in_sizes, int n_in,
                              void* d_out, int out_size) {
    const float* X      = (const float*)d_in[0];
    const float* ew     = (const float*)d_in[1];
    const float* p      = (const float*)d_in[2];
    const float* W_ih   = (const float*)d_in[3];
    const float* W_hh   = (const float*)d_in[4];
    const float* b_ih   = (const float*)d_in[5];
    const float* b_hh   = (const float*)d_in[6];
    const float* W_conv = (const float*)d_in[7];
    const float* b_conv = (const float*)d_in[8];
    const int*   ei     = (const int*)d_in[9];     // int32 (JAX x64 disabled)
    float* out = (float*)d_out;

    const int GRU_SMEM   = (64 * 129 + 32 * 128) * sizeof(float);    // 49408 B
    const int GEMM2_SMEM = (128 * 68 + 128 * 130) * sizeof(float);   // 101376 B
    cudaFuncSetAttribute(k_gru,   cudaFuncAttributeMaxDynamicSharedMemorySize, GRU_SMEM);
    cudaFuncSetAttribute(k_gemm2, cudaFuncAttributeMaxDynamicSharedMemorySize, GEMM2_SMEM);

    // ---- fork at t=0: chain B (topk/GRU) on side stream ----
    cudaEventRecord(hx.evf, 0);
    cudaStreamWaitEvent(hx.s1, hx.evf, 0);

    k_initB <<<256, 256, 0, hx.s1>>>();
    k_gru   <<<dim3(4, 6), 256, GRU_SMEM, hx.s1>>>(1, W_conv, W_ih, W_hh);  // gh: no deps
    k_score <<<(N_NODES + 7) / 8, 256, 0, hx.s1>>>(X, p);
    k_select<<<1, 1024, 0, hx.s1>>>(X);
    k_gru   <<<dim3(4, 6), 256, GRU_SMEM, hx.s1>>>(0, W_conv, W_ih, W_hh);  // gi: needs Xt
    k_gates <<<64, 256, 0, hx.s1>>>(b_ih, b_hh, W_conv);
    cudaEventRecord(hx.evj, hx.s1);

    // ---- chain A (edge/agg) on main stream: initA -> bucket -> dinv -> agg ----
    k_initA <<<(N_NODES + 255) / 256, 256>>>();
    k_bucket<<<(E_EDGES + 255) / 256, 256>>>(ei, ew);
    k_dinv  <<<(N_NODES + 255) / 256, 256>>>();
    k_agg   <<<(N_NODES * 32 + 255) / 256, 256>>>(X);

    // ---- join, then final GEMM ----
    cudaStreamWaitEvent(0, hx.evj, 0);
    k_gemm2<<<(N_NODES + 63) / 64, 256, GEMM2_SMEM>>>(out, b_conv);
}